// round 15
// baseline (speedup 1.0000x reference)
#include <cuda_runtime.h>
#include <cstdint>
#include <cstddef>

#define NIMG 32
#define CIN  128
#define HH   64
#define WW   64
#define COUTC 256
#define NTILES (NIMG * 32 * 32)   // 32768 Winograd 2x2 output tiles

// scratch (allocation-free: __device__ globals)
// g_v / g_u are stored PRE-SWIZZLED: within each 128B row, 16B chunk c lives at chunk (c ^ (row&7)).
__device__ __align__(16) unsigned char g_x8[(size_t)NIMG * HH * WW * CIN];  // packed x, [n][h][w][cin] 0/1
__device__ __align__(16) unsigned char g_v[(size_t)16 * NTILES * CIN];      // V = Bt d B, [pos][tile][cin] s8, swizzled
__device__ __align__(16) unsigned char g_u[16 * COUTC * CIN];               // U = 4 G g Gt, [pos][cout][cin] s8, swizzled

// ---------------- Phase A: x fp32 NCHW -> s8 NHWC (0/1) ----------------
__global__ __launch_bounds__(128) void conv_x_kernel(const float* __restrict__ x) {
    int p = blockIdx.x * 128 + threadIdx.x;        // (n,h,w) flat
    int w = p & 63, h = (p >> 6) & 63, n = p >> 12;
    const float* xp = x + (size_t)n * CIN * HH * WW + h * WW + w;
    unsigned char* op = g_x8 + (size_t)p * CIN;
#pragma unroll
    for (int c16 = 0; c16 < 8; c16++) {
        uint32_t u[4];
#pragma unroll
        for (int q = 0; q < 4; q++) {
            uint32_t pk = 0;
#pragma unroll
            for (int j = 0; j < 4; j++) {
                float v = xp[(size_t)(c16 * 16 + q * 4 + j) * (HH * WW)];
                pk |= (v != 0.0f ? 1u : 0u) << (8 * j);
            }
            u[q] = pk;
        }
        *(uint4*)(op + c16 * 16) = make_uint4(u[0], u[1], u[2], u[3]);
    }
}

// ---------------- Phase B1: input Winograd transform V = Bt d B (swizzled store) ----------------
__global__ __launch_bounds__(256) void wino_x_kernel() {
    int t = blockIdx.x * 256 + threadIdx.x;        // NTILES*32 threads
    int chunk = t & 31, tile = t >> 5;             // chunk: 4B unit 0..31
    int n = tile >> 10, th = (tile >> 5) & 31, tw = tile & 31;
    const unsigned char* xn = g_x8 + (size_t)n * HH * WW * CIN + chunk * 4;

    uint32_t d[4][4];
#pragma unroll
    for (int i = 0; i < 4; i++) {
        int h = 2 * th - 1 + i;
#pragma unroll
        for (int j = 0; j < 4; j++) {
            int w = 2 * tw - 1 + j;
            d[i][j] = ((unsigned)h < 64u && (unsigned)w < 64u)
                ? *(const uint32_t*)(xn + (size_t)(h * 64 + w) * CIN) : 0u;
        }
    }
    uint32_t T[4][4], V[4][4];
#pragma unroll
    for (int j = 0; j < 4; j++) {
        T[0][j] = __vsub4(d[0][j], d[2][j]);
        T[1][j] = __vadd4(d[1][j], d[2][j]);
        T[2][j] = __vsub4(d[2][j], d[1][j]);
        T[3][j] = __vsub4(d[1][j], d[3][j]);
    }
#pragma unroll
    for (int i = 0; i < 4; i++) {
        V[i][0] = __vsub4(T[i][0], T[i][2]);
        V[i][1] = __vadd4(T[i][1], T[i][2]);
        V[i][2] = __vsub4(T[i][2], T[i][1]);
        V[i][3] = __vsub4(T[i][1], T[i][3]);
    }
    // swizzled store: 16B chunk (chunk>>2) -> (chunk>>2) ^ (tile&7)
    uint32_t swoff = ((uint32_t)((chunk >> 2) ^ (tile & 7)) << 4) + (chunk & 3) * 4;
#pragma unroll
    for (int i = 0; i < 4; i++)
#pragma unroll
        for (int j = 0; j < 4; j++)
            *(uint32_t*)(g_v + ((size_t)(i * 4 + j) * NTILES + tile) * CIN + swoff) = V[i][j];
}

// ---------------- Phase B2: weight Winograd transform U = G2 g G2t (swizzled store) ----------------
__global__ __launch_bounds__(256) void wino_w_kernel(const float* __restrict__ wgt) {
    int t = blockIdx.x * 256 + threadIdx.x;        // COUTC*CIN threads
    if (t >= COUTC * CIN) return;
    int co = t >> 7, ci = t & 127;
    const float* g = wgt + ((size_t)co * CIN + ci) * 9;
    int gg[3][3];
#pragma unroll
    for (int r = 0; r < 3; r++)
#pragma unroll
        for (int c = 0; c < 3; c++) {
            float v = g[r * 3 + c];
            gg[r][c] = (v > 0.5f) ? 1 : (v < -0.5f ? -1 : 0);
        }
    int T[4][3];
#pragma unroll
    for (int c = 0; c < 3; c++) {
        T[0][c] = 2 * gg[0][c];
        T[1][c] = gg[0][c] + gg[1][c] + gg[2][c];
        T[2][c] = gg[0][c] - gg[1][c] + gg[2][c];
        T[3][c] = 2 * gg[2][c];
    }
    uint32_t swoff = ((uint32_t)((ci >> 4) ^ (co & 7)) << 4) + (ci & 15);
#pragma unroll
    for (int i = 0; i < 4; i++) {
        int u[4];
        u[0] = 2 * T[i][0];
        u[1] = T[i][0] + T[i][1] + T[i][2];
        u[2] = T[i][0] - T[i][1] + T[i][2];
        u[3] = 2 * T[i][2];
#pragma unroll
        for (int j = 0; j < 4; j++)
            ((signed char*)g_u)[((size_t)(i * 4 + j) * COUTC + co) * CIN + swoff] = (signed char)u[j];
    }
}

// ---------------- Phase C: 16-position GEMM + incremental inverse transform ----------------
// CTA (256 thr, 2 CTAs/SM): 128 couts (one half) x 32 tiles (1 tile-row).
// EVERY warp is hybrid: owns 32 couts x 16 tiles; computes tiles[0..8) via mma.sync
// and tiles[8..16) via dp4a -> both pipes fed from every warp, symmetric stage times.
// Pipeline: 8 stages of 2 positions; fills via cp.async.bulk + mbarrier; co-resident
// CTA groups process stages in rotated order (stagger) to decorrelate bursts.
#define A_BYTES   16384                      // 128 rows x 128B
#define B_BYTES   4096                       // 32 rows x 128B
#define STAGE_BYTES (2 * (A_BYTES + B_BYTES))  // 40960
#define OFF_A(p)  ((p) * A_BYTES)
#define OFF_B(p)  (2 * A_BYTES + (p) * B_BYTES)
#define SMEM_MBAR (2 * STAGE_BYTES)          // 81920
#define SMEM_TOT  (SMEM_MBAR + 64)

__device__ __forceinline__ uint32_t smem_u32(const void* p) {
    uint32_t a;
    asm("{ .reg .u64 t; cvta.to.shared.u64 t, %1; cvt.u32.u64 %0, t; }" : "=r"(a) : "l"(p));
    return a;
}

#define MBAR_INIT(mb, cnt) \
    asm volatile("mbarrier.init.shared.b64 [%0], %1;" :: "r"((uint32_t)(mb)), "r"((uint32_t)(cnt)) : "memory")
#define MBAR_EXPECT(mb, bytes) \
    asm volatile("mbarrier.arrive.expect_tx.shared.b64 _, [%0], %1;" :: "r"((uint32_t)(mb)), "r"((uint32_t)(bytes)) : "memory")
#define BULK_CP(dst, src, bytes, mb) \
    asm volatile("cp.async.bulk.shared::cta.global.mbarrier::complete_tx::bytes [%0], [%1], %2, [%3];" \
                 :: "r"((uint32_t)(dst)), "l"(src), "r"((uint32_t)(bytes)), "r"((uint32_t)(mb)) : "memory")
#define MBAR_WAIT(mb, par) do {                                                        \
    uint32_t _m = (mb), _p = (par), _d = 0;                                            \
    while (!_d) {                                                                      \
        asm volatile("{ .reg .pred P; mbarrier.try_wait.parity.shared.b64 P, [%1], %2; selp.b32 %0,1,0,P; }" \
                     : "=r"(_d) : "r"(_m), "r"(_p) : "memory");                        \
    }                                                                                  \
} while (0)

#define LDSM_X4(r, addr)                                                               \
    asm volatile("ldmatrix.sync.aligned.m8n8.x4.shared.b16 {%0,%1,%2,%3}, [%4];"       \
                 : "=r"((r)[0]), "=r"((r)[1]), "=r"((r)[2]), "=r"((r)[3])              \
                 : "r"(addr))
#define LDSM_X2(r0, r1, addr)                                                          \
    asm volatile("ldmatrix.sync.aligned.m8n8.x2.shared.b16 {%0,%1}, [%2];"             \
                 : "=r"(r0), "=r"(r1)                                                  \
                 : "r"(addr))

#define MMA_S8(d, a, b0, b1)                                                           \
    asm volatile("mma.sync.aligned.m16n8k32.row.col.s32.s8.s8.s32 "                    \
                 "{%0,%1,%2,%3}, {%4,%5,%6,%7}, {%8,%9}, {%0,%1,%2,%3};"               \
                 : "+r"((d)[0]), "+r"((d)[1]), "+r"((d)[2]), "+r"((d)[3])              \
                 : "r"((a)[0]), "r"((a)[1]), "r"((a)[2]), "r"((a)[3]),                 \
                   "r"(b0), "r"(b1))

// A^T rows of F(2,3): r0 = [1,1,1,0], r1 = [0,1,-1,-1]
__device__ __forceinline__ constexpr int CA(int r, int p) {
    return r == 0 ? (p == 3 ? 0 : 1) : (p == 0 ? 0 : (p == 1 ? 1 : -1));
}

__global__ __launch_bounds__(256, 2) void conv_mma_kernel(
    const float* __restrict__ bias, const float* __restrict__ sgn, float* __restrict__ out)
{
    extern __shared__ char smem[];
    uint32_t smem_base = smem_u32(smem);
    int tid = threadIdx.x, wid = tid >> 5, lane = tid & 31;
    int b = blockIdx.x;
    int ch  = b & 1;            // cout half
    int tbk = b >> 1;           // 0..1023
    int n   = tbk >> 5;
    int th  = tbk & 31;         // tile-row (output rows 2th, 2th+1)
    int tile_base = n * 1024 + th * 32;
    int srot = ((b / 148) & 1) * 4;   // stagger co-resident CTA groups

    if (tid == 0) {
        MBAR_INIT(smem_base + SMEM_MBAR, 1);
        MBAR_INIT(smem_base + SMEM_MBAR + 8, 1);
    }
    __syncthreads();

    // ---- fill physical stage s with content stage ss = (s + srot) & 7 ----
    auto fill = [&](int s) {
        int ss = (s + srot) & 7;
        uint32_t sb = smem_base + (uint32_t)(s & 1) * STAGE_BYTES;
        uint32_t mb = smem_base + SMEM_MBAR + (uint32_t)(s & 1) * 8;
        MBAR_EXPECT(mb, STAGE_BYTES);
#pragma unroll
        for (int p = 0; p < 2; p++) {
            int pos = 2 * ss + p;
            BULK_CP(sb + OFF_A(p), g_u + ((size_t)pos * COUTC + ch * 128) * CIN, A_BYTES, mb);
            BULK_CP(sb + OFF_B(p), g_v + ((size_t)pos * NTILES + tile_base) * CIN, B_BYTES, mb);
        }
    };

    if (tid == 0) fill(0);

    // ---- per-warp addressing ----
    int cm    = (wid & 3) * 32;            // cout block within half
    int tbase = (wid >> 2) * 16;           // tile block base (16 tiles per warp)
    // tensor (tiles tbase..tbase+8): A frag rows
    uint32_t a_row = (uint32_t)(cm + (lane & 7) + ((lane >> 3) & 1) * 8);
    uint32_t a_rs  = a_row & 7;
    uint32_t a_hi  = (lane >> 4) & 1;
    uint32_t a_base = a_row * 128u;
    // B x2 frag: octet0 -> tiles k0-15 (b0), octet1 -> k16-31 (b1)
    uint32_t b_row = (uint32_t)(tbase + (lane & 7));
    uint32_t b_rs  = b_row & 7;
    uint32_t b_hi  = (lane >> 3) & 1;
    uint32_t b_base = b_row * 128u;
    // dp4a (tiles tbase+8..tbase+16): lane = cout-group x pixel-group
    int cg  = lane & 3;
    int pxg = lane >> 2;
    int xrow = tbase + 8 + pxg;

    int Yr[64];                           // 16 points x 4 (2x2 pixels); pts 0-7 tensor, 8-15 dp4a
#pragma unroll
    for (int i = 0; i < 64; i++) Yr[i] = 0;

#pragma unroll
    for (int s = 0; s < 8; s++) {
        MBAR_WAIT(smem_base + SMEM_MBAR + (uint32_t)(s & 1) * 8, (s >> 1) & 1);
        __syncthreads();
        if (s < 7 && tid == 0) fill(s + 1);

        int ss = (s + srot) & 7;
        uint32_t stage = smem_base + (uint32_t)(s & 1) * STAGE_BYTES;
#pragma unroll
        for (int p = 0; p < 2; p++) {
            const int pos = 2 * ss + p;
            const int pr = pos >> 2, pc = pos & 3;
            uint32_t A0 = stage + OFF_A(p);
            uint32_t B0 = stage + OFF_B(p);

            // ---------- tensor part: 32 cout x 8 tiles ----------
            {
                int M[2][4];
#pragma unroll
                for (int i = 0; i < 2; i++)
#pragma unroll
                    for (int q = 0; q < 4; q++) M[i][q] = 0;
#pragma unroll
                for (int kc = 0; kc < 4; kc++) {
                    uint32_t ca = (uint32_t)(kc * 2) + a_hi;
                    uint32_t cbk = (uint32_t)(kc * 2) + b_hi;
                    uint32_t af[2][4];
                    LDSM_X4(af[0], A0 + a_base + (((ca ^ a_rs) & 7u) << 4));
                    LDSM_X4(af[1], A0 + a_base + 16u * 128u + (((ca ^ a_rs) & 7u) << 4));
                    uint32_t bf0, bf1;
                    LDSM_X2(bf0, bf1, B0 + b_base + (((cbk ^ b_rs) & 7u) << 4));
                    MMA_S8(M[0], af[0], bf0, bf1);
                    MMA_S8(M[1], af[1], bf0, bf1);
                }
#pragma unroll
                for (int i = 0; i < 2; i++)
#pragma unroll
                    for (int reg = 0; reg < 4; reg++) {
                        int m = M[i][reg];
                        int base = (i * 4 + reg) * 4;
#pragma unroll
                        for (int r = 0; r < 2; r++)
#pragma unroll
                            for (int c = 0; c < 2; c++) {
                                const int k = CA(r, pr) * CA(c, pc);
                                if (k == 1)       Yr[base + r * 2 + c] += m;
                                else if (k == -1) Yr[base + r * 2 + c] -= m;
                            }
                    }
            }

            // ---------- dp4a part: 32 cout x 8 tiles ----------
            {
                int M2[8];
#pragma unroll
                for (int i = 0; i < 8; i++) M2[i] = 0;
#pragma unroll
                for (int k16 = 0; k16 < 8; k16++) {
                    int4 xv = *(const int4*)(smem + (B0 - smem_base) + xrow * 128 + (((k16 ^ (xrow & 7)) & 7) << 4));
#pragma unroll
                    for (int i = 0; i < 8; i++) {
                        int rw = cm + cg + 4 * i;
                        int4 wv = *(const int4*)(smem + (A0 - smem_base) + rw * 128 + (((k16 ^ (rw & 7)) & 7) << 4));
                        int s0 = M2[i];
                        s0 = __dp4a(xv.x, wv.x, s0); s0 = __dp4a(xv.y, wv.y, s0);
                        s0 = __dp4a(xv.z, wv.z, s0); s0 = __dp4a(xv.w, wv.w, s0);
                        M2[i] = s0;
                    }
                }
#pragma unroll
                for (int i = 0; i < 8; i++) {
                    int m = M2[i];
                    int base = (8 + i) * 4;
#pragma unroll
                    for (int r = 0; r < 2; r++)
#pragma unroll
                        for (int c = 0; c < 2; c++) {
                            const int k = CA(r, pr) * CA(c, pc);
                            if (k == 1)       Yr[base + r * 2 + c] += m;
                            else if (k == -1) Yr[base + r * 2 + c] -= m;
                        }
                }
            }
        }
    }

    // ---- epilogue: y = Y/4 + bias; out = (y*sign >= 0). Compare 4y vs -4bias (exact). ----
    // tensor points
    {
        int gq = lane >> 2, tig = lane & 3;
#pragma unroll
        for (int i = 0; i < 2; i++)
#pragma unroll
            for (int reg = 0; reg < 4; reg++) {
                int cout = ch * 128 + cm + i * 16 + (reg >> 1) * 8 + gq;
                int tw = tbase + 2 * tig + (reg & 1);
                float b4 = 4.0f * bias[cout];
                float sv = sgn[cout];
                int base = (i * 4 + reg) * 4;
#pragma unroll
                for (int r = 0; r < 2; r++) {
                    float f0 = (float)Yr[base + r * 2 + 0] + b4;
                    float f1 = (float)Yr[base + r * 2 + 1] + b4;
                    float2 o;
                    o.x = (f0 * sv >= 0.0f) ? 1.0f : 0.0f;
                    o.y = (f1 * sv >= 0.0f) ? 1.0f : 0.0f;
                    *(float2*)(out + (((size_t)n * COUTC + cout) * HH + 2 * th + r) * WW + 2 * tw) = o;
                }
            }
    }
    // dp4a points
    {
#pragma unroll
        for (int i = 0; i < 8; i++) {
            int cout = ch * 128 + cm + cg + 4 * i;
            int tw = xrow - tile_base % 1;          // = tbase + 8 + pxg (local tile idx)
            tw = tbase + 8 + pxg;
            float b4 = 4.0f * bias[cout];
            float sv = sgn[cout];
            int base = (8 + i) * 4;
#pragma unroll
            for (int r = 0; r < 2; r++) {
                float f0 = (float)Yr[base + r * 2 + 0] + b4;
                float f1 = (float)Yr[base + r * 2 + 1] + b4;
                float2 o;
                o.x = (f0 * sv >= 0.0f) ? 1.0f : 0.0f;
                o.y = (f1 * sv >= 0.0f) ? 1.0f : 0.0f;
                *(float2*)(out + (((size_t)n * COUTC + cout) * HH + 2 * th + r) * WW + 2 * tw) = o;
            }
        }
    }
}

// ---------------- launch ----------------
extern "C" void kernel_launch(void* const* d_in, const int* in_sizes, int n_in,
                              void* d_out, int out_size) {
    const float* x    = (const float*)d_in[0];
    const float* wgt  = (const float*)d_in[1];
    const float* bias = (const float*)d_in[2];
    const float* sgn  = (const float*)d_in[3];
    float* out = (float*)d_out;

    cudaFuncSetAttribute(conv_mma_kernel, cudaFuncAttributeMaxDynamicSharedMemorySize, SMEM_TOT);

    conv_x_kernel<<<(NIMG * HH * WW) / 128, 128>>>(x);
    wino_x_kernel<<<(NTILES * 32) / 256, 256>>>();
    wino_w_kernel<<<(COUTC * CIN) / 256, 256>>>(wgt);
    conv_mma_kernel<<<NIMG * 32 * 2, 256, SMEM_TOT>>>(bias, sgn, out);
}

// round 16
// speedup vs baseline: 1.3253x; 1.3253x over previous
#include <cuda_runtime.h>
#include <cstdint>
#include <cstddef>

#define NIMG 32
#define CIN  128
#define HH   64
#define WW   64
#define COUTC 256
#define NTILES (NIMG * 32 * 32)   // 32768 Winograd 2x2 output tiles

// scratch (allocation-free: __device__ globals)
// g_v / g_u are stored PRE-SWIZZLED: within each 128B row, 16B chunk c lives at chunk (c ^ (row&7)).
__device__ __align__(16) unsigned char g_x8[(size_t)NIMG * HH * WW * CIN];  // packed x, [n][h][w][cin] 0/1
__device__ __align__(16) unsigned char g_v[(size_t)16 * NTILES * CIN];      // V = Bt d B, [pos][tile][cin] s8, swizzled
__device__ __align__(16) unsigned char g_u[16 * COUTC * CIN];               // U = 4 G g Gt, [pos][cout][cin] s8, swizzled

// ---------------- Phase A: x fp32 NCHW -> s8 NHWC (0/1) ----------------
__global__ __launch_bounds__(128) void conv_x_kernel(const float* __restrict__ x) {
    int p = blockIdx.x * 128 + threadIdx.x;        // (n,h,w) flat
    int w = p & 63, h = (p >> 6) & 63, n = p >> 12;
    const float* xp = x + (size_t)n * CIN * HH * WW + h * WW + w;
    unsigned char* op = g_x8 + (size_t)p * CIN;
#pragma unroll
    for (int c16 = 0; c16 < 8; c16++) {
        uint32_t u[4];
#pragma unroll
        for (int q = 0; q < 4; q++) {
            uint32_t pk = 0;
#pragma unroll
            for (int j = 0; j < 4; j++) {
                float v = xp[(size_t)(c16 * 16 + q * 4 + j) * (HH * WW)];
                pk |= (v != 0.0f ? 1u : 0u) << (8 * j);
            }
            u[q] = pk;
        }
        *(uint4*)(op + c16 * 16) = make_uint4(u[0], u[1], u[2], u[3]);
    }
}

// ---------------- Phase B1: input Winograd transform V = Bt d B (swizzled store) ----------------
__global__ __launch_bounds__(256) void wino_x_kernel() {
    int t = blockIdx.x * 256 + threadIdx.x;        // NTILES*32 threads
    int chunk = t & 31, tile = t >> 5;             // chunk: 4B unit 0..31
    int n = tile >> 10, th = (tile >> 5) & 31, tw = tile & 31;
    const unsigned char* xn = g_x8 + (size_t)n * HH * WW * CIN + chunk * 4;

    uint32_t d[4][4];
#pragma unroll
    for (int i = 0; i < 4; i++) {
        int h = 2 * th - 1 + i;
#pragma unroll
        for (int j = 0; j < 4; j++) {
            int w = 2 * tw - 1 + j;
            d[i][j] = ((unsigned)h < 64u && (unsigned)w < 64u)
                ? *(const uint32_t*)(xn + (size_t)(h * 64 + w) * CIN) : 0u;
        }
    }
    uint32_t T[4][4], V[4][4];
#pragma unroll
    for (int j = 0; j < 4; j++) {
        T[0][j] = __vsub4(d[0][j], d[2][j]);
        T[1][j] = __vadd4(d[1][j], d[2][j]);
        T[2][j] = __vsub4(d[2][j], d[1][j]);
        T[3][j] = __vsub4(d[1][j], d[3][j]);
    }
#pragma unroll
    for (int i = 0; i < 4; i++) {
        V[i][0] = __vsub4(T[i][0], T[i][2]);
        V[i][1] = __vadd4(T[i][1], T[i][2]);
        V[i][2] = __vsub4(T[i][2], T[i][1]);
        V[i][3] = __vsub4(T[i][1], T[i][3]);
    }
    // swizzled store: 16B chunk (chunk>>2) -> (chunk>>2) ^ (tile&7)
    uint32_t swoff = ((uint32_t)((chunk >> 2) ^ (tile & 7)) << 4) + (chunk & 3) * 4;
#pragma unroll
    for (int i = 0; i < 4; i++)
#pragma unroll
        for (int j = 0; j < 4; j++)
            *(uint32_t*)(g_v + ((size_t)(i * 4 + j) * NTILES + tile) * CIN + swoff) = V[i][j];
}

// ---------------- Phase B2: weight Winograd transform U = G2 g G2t (swizzled store) ----------------
__global__ __launch_bounds__(256) void wino_w_kernel(const float* __restrict__ wgt) {
    int t = blockIdx.x * 256 + threadIdx.x;        // COUTC*CIN threads
    if (t >= COUTC * CIN) return;
    int co = t >> 7, ci = t & 127;
    const float* g = wgt + ((size_t)co * CIN + ci) * 9;
    int gg[3][3];
#pragma unroll
    for (int r = 0; r < 3; r++)
#pragma unroll
        for (int c = 0; c < 3; c++) {
            float v = g[r * 3 + c];
            gg[r][c] = (v > 0.5f) ? 1 : (v < -0.5f ? -1 : 0);
        }
    int T[4][3];
#pragma unroll
    for (int c = 0; c < 3; c++) {
        T[0][c] = 2 * gg[0][c];
        T[1][c] = gg[0][c] + gg[1][c] + gg[2][c];
        T[2][c] = gg[0][c] - gg[1][c] + gg[2][c];
        T[3][c] = 2 * gg[2][c];
    }
    uint32_t swoff = ((uint32_t)((ci >> 4) ^ (co & 7)) << 4) + (ci & 15);
#pragma unroll
    for (int i = 0; i < 4; i++) {
        int u[4];
        u[0] = 2 * T[i][0];
        u[1] = T[i][0] + T[i][1] + T[i][2];
        u[2] = T[i][0] - T[i][1] + T[i][2];
        u[3] = 2 * T[i][2];
#pragma unroll
        for (int j = 0; j < 4; j++)
            ((signed char*)g_u)[((size_t)(i * 4 + j) * COUTC + co) * CIN + swoff] = (signed char)u[j];
    }
}

// ---------------- Phase C: 16-position GEMM + incremental inverse transform ----------------
// CTA (512 thr, 1 CTA/SM): 128 couts (one half) x 32 tiles (1 tile-row).
//   warps 0-7 : tensor, 16 couts each x tiles 0-23 (3 n-tiles, 12 MMA/pos)
//   warps 8-15: dp4a,   32 couts x 4 tiles each, tiles 24-31 (thread: 4c x 1t)
// Pipeline: 4 stages of 4 positions (few syncs, long runs); bulk-copy fills.
#define A_BYTES   16384                      // 128 rows x 128B
#define B_BYTES   4096                       // 32 rows x 128B
#define POS_BYTES (A_BYTES + B_BYTES)        // 20480
#define STAGE_BYTES (4 * POS_BYTES)          // 81920
#define OFF_A(p)  ((p) * POS_BYTES)
#define OFF_B(p)  ((p) * POS_BYTES + A_BYTES)
#define SMEM_MBAR (2 * STAGE_BYTES)          // 163840
#define SMEM_TOT  (SMEM_MBAR + 64)

__device__ __forceinline__ uint32_t smem_u32(const void* p) {
    uint32_t a;
    asm("{ .reg .u64 t; cvta.to.shared.u64 t, %1; cvt.u32.u64 %0, t; }" : "=r"(a) : "l"(p));
    return a;
}

#define MBAR_INIT(mb, cnt) \
    asm volatile("mbarrier.init.shared.b64 [%0], %1;" :: "r"((uint32_t)(mb)), "r"((uint32_t)(cnt)) : "memory")
#define MBAR_EXPECT(mb, bytes) \
    asm volatile("mbarrier.arrive.expect_tx.shared.b64 _, [%0], %1;" :: "r"((uint32_t)(mb)), "r"((uint32_t)(bytes)) : "memory")
#define BULK_CP(dst, src, bytes, mb) \
    asm volatile("cp.async.bulk.shared::cta.global.mbarrier::complete_tx::bytes [%0], [%1], %2, [%3];" \
                 :: "r"((uint32_t)(dst)), "l"(src), "r"((uint32_t)(bytes)), "r"((uint32_t)(mb)) : "memory")
#define MBAR_WAIT(mb, par) do {                                                        \
    uint32_t _m = (mb), _p = (par), _d = 0;                                            \
    while (!_d) {                                                                      \
        asm volatile("{ .reg .pred P; mbarrier.try_wait.parity.shared.b64 P, [%1], %2; selp.b32 %0,1,0,P; }" \
                     : "=r"(_d) : "r"(_m), "r"(_p) : "memory");                        \
    }                                                                                  \
} while (0)

#define LDSM_X4(r, addr)                                                               \
    asm volatile("ldmatrix.sync.aligned.m8n8.x4.shared.b16 {%0,%1,%2,%3}, [%4];"       \
                 : "=r"((r)[0]), "=r"((r)[1]), "=r"((r)[2]), "=r"((r)[3])              \
                 : "r"(addr))
#define LDSM_X2(r0, r1, addr)                                                          \
    asm volatile("ldmatrix.sync.aligned.m8n8.x2.shared.b16 {%0,%1}, [%2];"             \
                 : "=r"(r0), "=r"(r1)                                                  \
                 : "r"(addr))

#define MMA_S8(d, a, b0, b1)                                                           \
    asm volatile("mma.sync.aligned.m16n8k32.row.col.s32.s8.s8.s32 "                    \
                 "{%0,%1,%2,%3}, {%4,%5,%6,%7}, {%8,%9}, {%0,%1,%2,%3};"               \
                 : "+r"((d)[0]), "+r"((d)[1]), "+r"((d)[2]), "+r"((d)[3])              \
                 : "r"((a)[0]), "r"((a)[1]), "r"((a)[2]), "r"((a)[3]),                 \
                   "r"(b0), "r"(b1))

// A^T rows of F(2,3): r0 = [1,1,1,0], r1 = [0,1,-1,-1]
__device__ __forceinline__ constexpr int CA(int r, int p) {
    return r == 0 ? (p == 3 ? 0 : 1) : (p == 0 ? 0 : (p == 1 ? 1 : -1));
}

__global__ __launch_bounds__(512, 1) void conv_mma_kernel(
    const float* __restrict__ bias, const float* __restrict__ sgn, float* __restrict__ out)
{
    extern __shared__ char smem[];
    uint32_t smem_base = smem_u32(smem);
    int tid = threadIdx.x, wid = tid >> 5, lane = tid & 31;
    int b = blockIdx.x;
    int ch  = b & 1;            // cout half
    int tbk = b >> 1;           // 0..1023
    int n   = tbk >> 5;
    int th  = tbk & 31;         // tile-row (output rows 2th, 2th+1)
    int tile_base = n * 1024 + th * 32;

    if (tid == 0) {
        MBAR_INIT(smem_base + SMEM_MBAR, 1);
        MBAR_INIT(smem_base + SMEM_MBAR + 8, 1);
    }
    __syncthreads();

    // ---- fill one stage (4 positions): 8 bulk copies from one thread ----
    auto fill = [&](int s) {
        uint32_t sb = smem_base + (uint32_t)(s & 1) * STAGE_BYTES;
        uint32_t mb = smem_base + SMEM_MBAR + (uint32_t)(s & 1) * 8;
        MBAR_EXPECT(mb, STAGE_BYTES);
#pragma unroll
        for (int p = 0; p < 4; p++) {
            int pos = 4 * s + p;
            BULK_CP(sb + OFF_A(p), g_u + ((size_t)pos * COUTC + ch * 128) * CIN, A_BYTES, mb);
            BULK_CP(sb + OFF_B(p), g_v + ((size_t)pos * NTILES + tile_base) * CIN, B_BYTES, mb);
        }
    };

    if (tid == 0) fill(0);

    // ---- per-warp addressing ----
    // tensor (wid<8): warp owns couts [wid*16, wid*16+16) x tiles 0..23
    uint32_t a_row = (uint32_t)(wid * 16 + (lane & 15));        // m16 frag rows
    uint32_t a_rs  = a_row & 7;
    uint32_t a_hi  = (uint32_t)((lane >> 4) & 1);               // k 16B-half
    uint32_t a_base = a_row * 128u;
    uint32_t b_row01 = (uint32_t)((lane & 7) + ((lane >> 4) & 1) * 8);  // ntiles 0,1 (x4)
    uint32_t b_row2  = (uint32_t)(16 + (lane & 7));                     // ntile 2 (x2)
    uint32_t b_hi  = (uint32_t)((lane >> 3) & 1);
    // dp4a (wid>=8): widx -> 32-cout block + 4-tile block within tiles 24..31
    int widx = wid - 8;
    int cb  = (widx & 3) * 32;
    int tb  = 24 + (widx >> 2) * 4;
    int cg  = lane & 7;           // cout lane: couts cb+cg+8*i, i<4
    int px  = lane >> 3;          // tile lane: tile tb+px
    int xrow = tb + px;

    int Yr[48];                   // tensor: 12 pts x 4 ; dp4a: 4 pts x 4 (first 16 used)
#pragma unroll
    for (int i = 0; i < 48; i++) Yr[i] = 0;

#pragma unroll
    for (int s = 0; s < 4; s++) {
        MBAR_WAIT(smem_base + SMEM_MBAR + (uint32_t)(s & 1) * 8, (s >> 1) & 1);
        __syncthreads();
        if (s < 3 && tid == 0) fill(s + 1);

        uint32_t stage = smem_base + (uint32_t)(s & 1) * STAGE_BYTES;
#pragma unroll
        for (int p = 0; p < 4; p++) {
            const int pos = 4 * s + p;
            const int pr = pos >> 2, pc = pos & 3;
            uint32_t A0 = stage + OFF_A(p);
            uint32_t B0 = stage + OFF_B(p);

            if (wid < 8) {
                // ---------- tensor: 16 couts x 24 tiles = 12 MMA ----------
                int M[3][4];
#pragma unroll
                for (int i = 0; i < 3; i++)
#pragma unroll
                    for (int q = 0; q < 4; q++) M[i][q] = 0;
#pragma unroll
                for (int kc = 0; kc < 4; kc++) {
                    uint32_t ca  = (uint32_t)(kc * 2) + a_hi;
                    uint32_t cbk = (uint32_t)(kc * 2) + b_hi;
                    uint32_t af[4];
                    LDSM_X4(af, A0 + a_base + (((ca ^ a_rs) & 7u) << 4));
                    uint32_t bf[4];
                    LDSM_X4(bf, B0 + b_row01 * 128u + (((cbk ^ (b_row01 & 7u)) & 7u) << 4));
                    uint32_t b20, b21;
                    LDSM_X2(b20, b21, B0 + b_row2 * 128u + (((cbk ^ (b_row2 & 7u)) & 7u) << 4));
                    MMA_S8(M[0], af, bf[0], bf[1]);
                    MMA_S8(M[1], af, bf[2], bf[3]);
                    MMA_S8(M[2], af, b20, b21);
                }
#pragma unroll
                for (int nt = 0; nt < 3; nt++)
#pragma unroll
                    for (int reg = 0; reg < 4; reg++) {
                        int m = M[nt][reg];
                        int base = (nt * 4 + reg) * 4;
#pragma unroll
                        for (int r = 0; r < 2; r++)
#pragma unroll
                            for (int c = 0; c < 2; c++) {
                                const int k = CA(r, pr) * CA(c, pc);
                                if (k == 1)       Yr[base + r * 2 + c] += m;
                                else if (k == -1) Yr[base + r * 2 + c] -= m;
                            }
                    }
            } else {
                // ---------- dp4a: thread = 4 couts x 1 tile ----------
                int M2[4];
#pragma unroll
                for (int i = 0; i < 4; i++) M2[i] = 0;
#pragma unroll
                for (int k16 = 0; k16 < 8; k16++) {
                    int4 xv = *(const int4*)(smem + (B0 - smem_base) + xrow * 128 + (((k16 ^ (xrow & 7)) & 7) << 4));
#pragma unroll
                    for (int i = 0; i < 4; i++) {
                        int rw = cb + cg + 8 * i;
                        int4 wv = *(const int4*)(smem + (A0 - smem_base) + rw * 128 + (((k16 ^ (rw & 7)) & 7) << 4));
                        int s0 = M2[i];
                        s0 = __dp4a(xv.x, wv.x, s0); s0 = __dp4a(xv.y, wv.y, s0);
                        s0 = __dp4a(xv.z, wv.z, s0); s0 = __dp4a(xv.w, wv.w, s0);
                        M2[i] = s0;
                    }
                }
#pragma unroll
                for (int i = 0; i < 4; i++) {
                    int m = M2[i];
                    int base = i * 4;
#pragma unroll
                    for (int r = 0; r < 2; r++)
#pragma unroll
                        for (int c = 0; c < 2; c++) {
                            const int k = CA(r, pr) * CA(c, pc);
                            if (k == 1)       Yr[base + r * 2 + c] += m;
                            else if (k == -1) Yr[base + r * 2 + c] -= m;
                        }
                }
            }
        }
    }

    // ---- epilogue: y = Y/4 + bias; out = (y*sign >= 0). Compare 4y vs -4bias (exact). ----
    if (wid < 8) {
        int gq = lane >> 2, tig = lane & 3;
#pragma unroll
        for (int nt = 0; nt < 3; nt++)
#pragma unroll
            for (int reg = 0; reg < 4; reg++) {
                int cout = ch * 128 + wid * 16 + (reg >> 1) * 8 + gq;
                int tw = nt * 8 + 2 * tig + (reg & 1);
                float b4 = 4.0f * bias[cout];
                float sv = sgn[cout];
                int base = (nt * 4 + reg) * 4;
#pragma unroll
                for (int r = 0; r < 2; r++) {
                    float f0 = (float)Yr[base + r * 2 + 0] + b4;
                    float f1 = (float)Yr[base + r * 2 + 1] + b4;
                    float2 o;
                    o.x = (f0 * sv >= 0.0f) ? 1.0f : 0.0f;
                    o.y = (f1 * sv >= 0.0f) ? 1.0f : 0.0f;
                    *(float2*)(out + (((size_t)n * COUTC + cout) * HH + 2 * th + r) * WW + 2 * tw) = o;
                }
            }
    } else {
#pragma unroll
        for (int i = 0; i < 4; i++) {
            int cout = ch * 128 + cb + cg + 8 * i;
            int tw = tb + px;
            float b4 = 4.0f * bias[cout];
            float sv = sgn[cout];
            int base = i * 4;
#pragma unroll
            for (int r = 0; r < 2; r++) {
                float f0 = (float)Yr[base + r * 2 + 0] + b4;
                float f1 = (float)Yr[base + r * 2 + 1] + b4;
                float2 o;
                o.x = (f0 * sv >= 0.0f) ? 1.0f : 0.0f;
                o.y = (f1 * sv >= 0.0f) ? 1.0f : 0.0f;
                *(float2*)(out + (((size_t)n * COUTC + cout) * HH + 2 * th + r) * WW + 2 * tw) = o;
            }
        }
    }
}

// ---------------- launch ----------------
extern "C" void kernel_launch(void* const* d_in, const int* in_sizes, int n_in,
                              void* d_out, int out_size) {
    const float* x    = (const float*)d_in[0];
    const float* wgt  = (const float*)d_in[1];
    const float* bias = (const float*)d_in[2];
    const float* sgn  = (const float*)d_in[3];
    float* out = (float*)d_out;

    cudaFuncSetAttribute(conv_mma_kernel, cudaFuncAttributeMaxDynamicSharedMemorySize, SMEM_TOT);

    conv_x_kernel<<<(NIMG * HH * WW) / 128, 128>>>(x);
    wino_x_kernel<<<(NTILES * 32) / 256, 256>>>();
    wino_w_kernel<<<(COUTC * CIN) / 256, 256>>>(wgt);
    conv_mma_kernel<<<NIMG * 32 * 2, 512, SMEM_TOT>>>(bias, sgn, out);
}

// round 17
// speedup vs baseline: 1.4972x; 1.1297x over previous
#include <cuda_runtime.h>
#include <cstdint>
#include <cstddef>

#define NIMG 32
#define CIN  128
#define HH   64
#define WW   64
#define COUTC 256
#define NTILES (NIMG * 32 * 32)   // 32768 Winograd 2x2 output tiles

// scratch (allocation-free: __device__ globals)
// g_v / g_u are stored PRE-SWIZZLED: within each 128B row, 16B chunk c lives at chunk (c ^ (row&7)).
__device__ __align__(16) unsigned char g_x8[(size_t)NIMG * HH * WW * CIN];  // packed x, [n][h][w][cin] 0/1
__device__ __align__(16) unsigned char g_v[(size_t)16 * NTILES * CIN];      // V = Bt d B, [pos][tile][cin] s8, swizzled
__device__ __align__(16) unsigned char g_u[16 * COUTC * CIN];               // U = 4 G g Gt, [pos][cout][cin] s8, swizzled

// ---------------- Phase A: x fp32 NCHW -> s8 NHWC (0/1) ----------------
__global__ __launch_bounds__(128) void conv_x_kernel(const float* __restrict__ x) {
    int p = blockIdx.x * 128 + threadIdx.x;        // (n,h,w) flat
    int w = p & 63, h = (p >> 6) & 63, n = p >> 12;
    const float* xp = x + (size_t)n * CIN * HH * WW + h * WW + w;
    unsigned char* op = g_x8 + (size_t)p * CIN;
#pragma unroll
    for (int c16 = 0; c16 < 8; c16++) {
        uint32_t u[4];
#pragma unroll
        for (int q = 0; q < 4; q++) {
            uint32_t pk = 0;
#pragma unroll
            for (int j = 0; j < 4; j++) {
                float v = xp[(size_t)(c16 * 16 + q * 4 + j) * (HH * WW)];
                pk |= (v != 0.0f ? 1u : 0u) << (8 * j);
            }
            u[q] = pk;
        }
        *(uint4*)(op + c16 * 16) = make_uint4(u[0], u[1], u[2], u[3]);
    }
}

// ---------------- Phase B1: input Winograd transform V = Bt d B (swizzled store) ----------------
__global__ __launch_bounds__(256) void wino_x_kernel() {
    int t = blockIdx.x * 256 + threadIdx.x;        // NTILES*32 threads
    int chunk = t & 31, tile = t >> 5;             // chunk: 4B unit 0..31
    int n = tile >> 10, th = (tile >> 5) & 31, tw = tile & 31;
    const unsigned char* xn = g_x8 + (size_t)n * HH * WW * CIN + chunk * 4;

    uint32_t d[4][4];
#pragma unroll
    for (int i = 0; i < 4; i++) {
        int h = 2 * th - 1 + i;
#pragma unroll
        for (int j = 0; j < 4; j++) {
            int w = 2 * tw - 1 + j;
            d[i][j] = ((unsigned)h < 64u && (unsigned)w < 64u)
                ? *(const uint32_t*)(xn + (size_t)(h * 64 + w) * CIN) : 0u;
        }
    }
    uint32_t T[4][4], V[4][4];
#pragma unroll
    for (int j = 0; j < 4; j++) {
        T[0][j] = __vsub4(d[0][j], d[2][j]);
        T[1][j] = __vadd4(d[1][j], d[2][j]);
        T[2][j] = __vsub4(d[2][j], d[1][j]);
        T[3][j] = __vsub4(d[1][j], d[3][j]);
    }
#pragma unroll
    for (int i = 0; i < 4; i++) {
        V[i][0] = __vsub4(T[i][0], T[i][2]);
        V[i][1] = __vadd4(T[i][1], T[i][2]);
        V[i][2] = __vsub4(T[i][2], T[i][1]);
        V[i][3] = __vsub4(T[i][1], T[i][3]);
    }
    // swizzled store: 16B chunk (chunk>>2) -> (chunk>>2) ^ (tile&7)
    uint32_t swoff = ((uint32_t)((chunk >> 2) ^ (tile & 7)) << 4) + (chunk & 3) * 4;
#pragma unroll
    for (int i = 0; i < 4; i++)
#pragma unroll
        for (int j = 0; j < 4; j++)
            *(uint32_t*)(g_v + ((size_t)(i * 4 + j) * NTILES + tile) * CIN + swoff) = V[i][j];
}

// ---------------- Phase B2: weight Winograd transform U = G2 g G2t (swizzled store) ----------------
__global__ __launch_bounds__(256) void wino_w_kernel(const float* __restrict__ wgt) {
    int t = blockIdx.x * 256 + threadIdx.x;        // COUTC*CIN threads
    if (t >= COUTC * CIN) return;
    int co = t >> 7, ci = t & 127;
    const float* g = wgt + ((size_t)co * CIN + ci) * 9;
    int gg[3][3];
#pragma unroll
    for (int r = 0; r < 3; r++)
#pragma unroll
        for (int c = 0; c < 3; c++) {
            float v = g[r * 3 + c];
            gg[r][c] = (v > 0.5f) ? 1 : (v < -0.5f ? -1 : 0);
        }
    int T[4][3];
#pragma unroll
    for (int c = 0; c < 3; c++) {
        T[0][c] = 2 * gg[0][c];
        T[1][c] = gg[0][c] + gg[1][c] + gg[2][c];
        T[2][c] = gg[0][c] - gg[1][c] + gg[2][c];
        T[3][c] = 2 * gg[2][c];
    }
    uint32_t swoff = ((uint32_t)((ci >> 4) ^ (co & 7)) << 4) + (ci & 15);
#pragma unroll
    for (int i = 0; i < 4; i++) {
        int u[4];
        u[0] = 2 * T[i][0];
        u[1] = T[i][0] + T[i][1] + T[i][2];
        u[2] = T[i][0] - T[i][1] + T[i][2];
        u[3] = 2 * T[i][2];
#pragma unroll
        for (int j = 0; j < 4; j++)
            ((signed char*)g_u)[((size_t)(i * 4 + j) * COUTC + co) * CIN + swoff] = (signed char)u[j];
    }
}

// ---------------- Phase C: 16-position GEMM + incremental inverse transform ----------------
// CTA (512 thr, 1 CTA/SM): 128 couts (one half) x 32 tiles (1 tile-row).
// Balanced hybrid (tensor rt ~282 MAC/cyc/SM, dp4a ~256):
//   warps 0-7 : tensor, 16 couts each x tiles 0-15 (2 n-tiles, 8 MMA/pos)
//   warps 8-15: dp4a,   32 couts x 8 tiles each, tiles 16-31 (thread: 4c x 2t)
// Pipeline: 4 stages of 4 positions; bulk-copy fills.
#define A_BYTES   16384                      // 128 rows x 128B
#define B_BYTES   4096                       // 32 rows x 128B
#define POS_BYTES (A_BYTES + B_BYTES)        // 20480
#define STAGE_BYTES (4 * POS_BYTES)          // 81920
#define OFF_A(p)  ((p) * POS_BYTES)
#define OFF_B(p)  ((p) * POS_BYTES + A_BYTES)
#define SMEM_MBAR (2 * STAGE_BYTES)          // 163840
#define SMEM_TOT  (SMEM_MBAR + 64)

__device__ __forceinline__ uint32_t smem_u32(const void* p) {
    uint32_t a;
    asm("{ .reg .u64 t; cvta.to.shared.u64 t, %1; cvt.u32.u64 %0, t; }" : "=r"(a) : "l"(p));
    return a;
}

#define MBAR_INIT(mb, cnt) \
    asm volatile("mbarrier.init.shared.b64 [%0], %1;" :: "r"((uint32_t)(mb)), "r"((uint32_t)(cnt)) : "memory")
#define MBAR_EXPECT(mb, bytes) \
    asm volatile("mbarrier.arrive.expect_tx.shared.b64 _, [%0], %1;" :: "r"((uint32_t)(mb)), "r"((uint32_t)(bytes)) : "memory")
#define BULK_CP(dst, src, bytes, mb) \
    asm volatile("cp.async.bulk.shared::cta.global.mbarrier::complete_tx::bytes [%0], [%1], %2, [%3];" \
                 :: "r"((uint32_t)(dst)), "l"(src), "r"((uint32_t)(bytes)), "r"((uint32_t)(mb)) : "memory")
#define MBAR_WAIT(mb, par) do {                                                        \
    uint32_t _m = (mb), _p = (par), _d = 0;                                            \
    while (!_d) {                                                                      \
        asm volatile("{ .reg .pred P; mbarrier.try_wait.parity.shared.b64 P, [%1], %2; selp.b32 %0,1,0,P; }" \
                     : "=r"(_d) : "r"(_m), "r"(_p) : "memory");                        \
    }                                                                                  \
} while (0)

#define LDSM_X4(r, addr)                                                               \
    asm volatile("ldmatrix.sync.aligned.m8n8.x4.shared.b16 {%0,%1,%2,%3}, [%4];"       \
                 : "=r"((r)[0]), "=r"((r)[1]), "=r"((r)[2]), "=r"((r)[3])              \
                 : "r"(addr))

#define MMA_S8(d, a, b0, b1)                                                           \
    asm volatile("mma.sync.aligned.m16n8k32.row.col.s32.s8.s8.s32 "                    \
                 "{%0,%1,%2,%3}, {%4,%5,%6,%7}, {%8,%9}, {%0,%1,%2,%3};"               \
                 : "+r"((d)[0]), "+r"((d)[1]), "+r"((d)[2]), "+r"((d)[3])              \
                 : "r"((a)[0]), "r"((a)[1]), "r"((a)[2]), "r"((a)[3]),                 \
                   "r"(b0), "r"(b1))

// A^T rows of F(2,3): r0 = [1,1,1,0], r1 = [0,1,-1,-1]
__device__ __forceinline__ constexpr int CA(int r, int p) {
    return r == 0 ? (p == 3 ? 0 : 1) : (p == 0 ? 0 : (p == 1 ? 1 : -1));
}

__global__ __launch_bounds__(512, 1) void conv_mma_kernel(
    const float* __restrict__ bias, const float* __restrict__ sgn, float* __restrict__ out)
{
    extern __shared__ char smem[];
    uint32_t smem_base = smem_u32(smem);
    int tid = threadIdx.x, wid = tid >> 5, lane = tid & 31;
    int b = blockIdx.x;
    int ch  = b & 1;            // cout half
    int tbk = b >> 1;           // 0..1023
    int n   = tbk >> 5;
    int th  = tbk & 31;         // tile-row (output rows 2th, 2th+1)
    int tile_base = n * 1024 + th * 32;

    if (tid == 0) {
        MBAR_INIT(smem_base + SMEM_MBAR, 1);
        MBAR_INIT(smem_base + SMEM_MBAR + 8, 1);
    }
    __syncthreads();

    // ---- fill one stage (4 positions): 8 bulk copies from one thread ----
    auto fill = [&](int s) {
        uint32_t sb = smem_base + (uint32_t)(s & 1) * STAGE_BYTES;
        uint32_t mb = smem_base + SMEM_MBAR + (uint32_t)(s & 1) * 8;
        MBAR_EXPECT(mb, STAGE_BYTES);
#pragma unroll
        for (int p = 0; p < 4; p++) {
            int pos = 4 * s + p;
            BULK_CP(sb + OFF_A(p), g_u + ((size_t)pos * COUTC + ch * 128) * CIN, A_BYTES, mb);
            BULK_CP(sb + OFF_B(p), g_v + ((size_t)pos * NTILES + tile_base) * CIN, B_BYTES, mb);
        }
    };

    if (tid == 0) fill(0);

    // ---- per-warp addressing ----
    // tensor (wid<8): warp owns couts [wid*16, wid*16+16) x tiles 0..15
    uint32_t a_row = (uint32_t)(wid * 16 + (lane & 15));        // m16 frag rows
    uint32_t a_rs  = a_row & 7;
    uint32_t a_hi  = (uint32_t)((lane >> 4) & 1);               // k 16B-half
    uint32_t a_base = a_row * 128u;
    uint32_t b_row = (uint32_t)((lane & 7) + ((lane >> 4) & 1) * 8);  // ntiles 0,1 (x4)
    uint32_t b_rs  = b_row & 7;
    uint32_t b_hi  = (uint32_t)((lane >> 3) & 1);
    // dp4a (wid>=8): widx -> 32-cout block x 8-tile block within tiles 16..31
    int widx = wid - 8;
    int cb  = (widx & 3) * 32;
    int tb  = 16 + (widx >> 2) * 8;
    int cg  = lane & 7;           // cout lane: couts cb+cg+8*i, i<4
    int px  = lane >> 3;          // tile lane: tiles tb+px, tb+px+4
    int xr0 = tb + px, xr1 = tb + px + 4;

    int Yr[32];                   // tensor: 8 pts x 4 ; dp4a: 8 pts x 4
#pragma unroll
    for (int i = 0; i < 32; i++) Yr[i] = 0;

#pragma unroll
    for (int s = 0; s < 4; s++) {
        MBAR_WAIT(smem_base + SMEM_MBAR + (uint32_t)(s & 1) * 8, (s >> 1) & 1);
        __syncthreads();
        if (s < 3 && tid == 0) fill(s + 1);

        uint32_t stage = smem_base + (uint32_t)(s & 1) * STAGE_BYTES;
#pragma unroll
        for (int p = 0; p < 4; p++) {
            const int pos = 4 * s + p;
            const int pr = pos >> 2, pc = pos & 3;
            uint32_t A0 = stage + OFF_A(p);
            uint32_t B0 = stage + OFF_B(p);

            if (wid < 8) {
                // ---------- tensor: 16 couts x 16 tiles = 8 MMA ----------
                int M[2][4];
#pragma unroll
                for (int i = 0; i < 2; i++)
#pragma unroll
                    for (int q = 0; q < 4; q++) M[i][q] = 0;
#pragma unroll
                for (int kc = 0; kc < 4; kc++) {
                    uint32_t ca  = (uint32_t)(kc * 2) + a_hi;
                    uint32_t cbk = (uint32_t)(kc * 2) + b_hi;
                    uint32_t af[4];
                    LDSM_X4(af, A0 + a_base + (((ca ^ a_rs) & 7u) << 4));
                    uint32_t bf[4];
                    LDSM_X4(bf, B0 + b_row * 128u + (((cbk ^ b_rs) & 7u) << 4));
                    MMA_S8(M[0], af, bf[0], bf[1]);
                    MMA_S8(M[1], af, bf[2], bf[3]);
                }
#pragma unroll
                for (int nt = 0; nt < 2; nt++)
#pragma unroll
                    for (int reg = 0; reg < 4; reg++) {
                        int m = M[nt][reg];
                        int base = (nt * 4 + reg) * 4;
#pragma unroll
                        for (int r = 0; r < 2; r++)
#pragma unroll
                            for (int c = 0; c < 2; c++) {
                                const int k = CA(r, pr) * CA(c, pc);
                                if (k == 1)       Yr[base + r * 2 + c] += m;
                                else if (k == -1) Yr[base + r * 2 + c] -= m;
                            }
                    }
            } else {
                // ---------- dp4a: thread = 4 couts x 2 tiles ----------
                int M2[4][2];
#pragma unroll
                for (int i = 0; i < 4; i++) { M2[i][0] = 0; M2[i][1] = 0; }
#pragma unroll
                for (int k16 = 0; k16 < 8; k16++) {
                    int4 xv0 = *(const int4*)(smem + (B0 - smem_base) + xr0 * 128 + (((k16 ^ (xr0 & 7)) & 7) << 4));
                    int4 xv1 = *(const int4*)(smem + (B0 - smem_base) + xr1 * 128 + (((k16 ^ (xr1 & 7)) & 7) << 4));
#pragma unroll
                    for (int i = 0; i < 4; i++) {
                        int rw = cb + cg + 8 * i;
                        int4 wv = *(const int4*)(smem + (A0 - smem_base) + rw * 128 + (((k16 ^ (rw & 7)) & 7) << 4));
                        int s0 = M2[i][0], s1 = M2[i][1];
                        s0 = __dp4a(xv0.x, wv.x, s0); s0 = __dp4a(xv0.y, wv.y, s0);
                        s0 = __dp4a(xv0.z, wv.z, s0); s0 = __dp4a(xv0.w, wv.w, s0);
                        s1 = __dp4a(xv1.x, wv.x, s1); s1 = __dp4a(xv1.y, wv.y, s1);
                        s1 = __dp4a(xv1.z, wv.z, s1); s1 = __dp4a(xv1.w, wv.w, s1);
                        M2[i][0] = s0; M2[i][1] = s1;
                    }
                }
#pragma unroll
                for (int i = 0; i < 4; i++)
#pragma unroll
                    for (int j = 0; j < 2; j++) {
                        int m = M2[i][j];
                        int base = (i * 2 + j) * 4;
#pragma unroll
                        for (int r = 0; r < 2; r++)
#pragma unroll
                            for (int c = 0; c < 2; c++) {
                                const int k = CA(r, pr) * CA(c, pc);
                                if (k == 1)       Yr[base + r * 2 + c] += m;
                                else if (k == -1) Yr[base + r * 2 + c] -= m;
                            }
                    }
            }
        }
    }

    // ---- epilogue: y = Y/4 + bias; out = (y*sign >= 0). Compare 4y vs -4bias (exact). ----
    if (wid < 8) {
        int gq = lane >> 2, tig = lane & 3;
#pragma unroll
        for (int nt = 0; nt < 2; nt++)
#pragma unroll
            for (int reg = 0; reg < 4; reg++) {
                int cout = ch * 128 + wid * 16 + (reg >> 1) * 8 + gq;
                int tw = nt * 8 + 2 * tig + (reg & 1);
                float b4 = 4.0f * bias[cout];
                float sv = sgn[cout];
                int base = (nt * 4 + reg) * 4;
#pragma unroll
                for (int r = 0; r < 2; r++) {
                    float f0 = (float)Yr[base + r * 2 + 0] + b4;
                    float f1 = (float)Yr[base + r * 2 + 1] + b4;
                    float2 o;
                    o.x = (f0 * sv >= 0.0f) ? 1.0f : 0.0f;
                    o.y = (f1 * sv >= 0.0f) ? 1.0f : 0.0f;
                    *(float2*)(out + (((size_t)n * COUTC + cout) * HH + 2 * th + r) * WW + 2 * tw) = o;
                }
            }
    } else {
#pragma unroll
        for (int i = 0; i < 4; i++) {
            int cout = ch * 128 + cb + cg + 8 * i;
            float b4 = 4.0f * bias[cout];
            float sv = sgn[cout];
#pragma unroll
            for (int j = 0; j < 2; j++) {
                int tw = tb + px + 4 * j;
                int base = (i * 2 + j) * 4;
#pragma unroll
                for (int r = 0; r < 2; r++) {
                    float f0 = (float)Yr[base + r * 2 + 0] + b4;
                    float f1 = (float)Yr[base + r * 2 + 1] + b4;
                    float2 o;
                    o.x = (f0 * sv >= 0.0f) ? 1.0f : 0.0f;
                    o.y = (f1 * sv >= 0.0f) ? 1.0f : 0.0f;
                    *(float2*)(out + (((size_t)n * COUTC + cout) * HH + 2 * th + r) * WW + 2 * tw) = o;
                }
            }
        }
    }
}

// ---------------- launch ----------------
extern "C" void kernel_launch(void* const* d_in, const int* in_sizes, int n_in,
                              void* d_out, int out_size) {
    const float* x    = (const float*)d_in[0];
    const float* wgt  = (const float*)d_in[1];
    const float* bias = (const float*)d_in[2];
    const float* sgn  = (const float*)d_in[3];
    float* out = (float*)d_out;

    cudaFuncSetAttribute(conv_mma_kernel, cudaFuncAttributeMaxDynamicSharedMemorySize, SMEM_TOT);

    conv_x_kernel<<<(NIMG * HH * WW) / 128, 128>>>(x);
    wino_x_kernel<<<(NTILES * 32) / 256, 256>>>();
    wino_w_kernel<<<(COUTC * CIN) / 256, 256>>>(wgt);
    conv_mma_kernel<<<NIMG * 32 * 2, 512, SMEM_TOT>>>(bias, sgn, out);
}